// round 1
// baseline (speedup 1.0000x reference)
#include <cuda_runtime.h>
#include <math.h>

#define N_   32
#define C_   64
#define G_   4
#define CG   16
#define K_   9
#define H_   64
#define W_   64
#define HW   4096
#define OFFC 72      // 2*K*G offset channels
#define COUT 64
#define OG   16      // Cout per group

// Scratch (static device allocations are allowed; cudaMalloc is not)
__device__ float g_off[N_ * OFFC * HW];   // (N, 72, H, W)
__device__ float g_pre[N_ * COUT * HW];   // pre-norm conv output (no b_dc; it cancels)
__device__ float g_sum[N_ * COUT];
__device__ float g_sq [N_ * COUT];

__global__ void zero_stats_kernel() {
    int i = blockIdx.x * blockDim.x + threadIdx.x;
    if (i < N_ * COUT) { g_sum[i] = 0.f; g_sq[i] = 0.f; }
}

// Grouped 3x3 conv producing offsets: off[n][oc][h][w]
__global__ void offset_conv_kernel(const float* __restrict__ x,
                                   const float* __restrict__ w_off,
                                   const float* __restrict__ b_off) {
    __shared__ float sw[CG * K_];
    const int oc = blockIdx.y;
    const int n  = blockIdx.z;
    const int tid = threadIdx.x;
    if (tid < CG * K_) sw[tid] = w_off[oc * CG * K_ + tid];
    __syncthreads();

    const int p = blockIdx.x * blockDim.x + tid;
    const int h = p >> 6, w = p & 63;
    const int go = oc / 18;                 // 18 offset channels per group
    const float* xb = x + (n * C_ + go * CG) * HW;

    float acc = b_off[oc];
    #pragma unroll
    for (int ki = 0; ki < 3; ki++) {
        const int y = h + ki - 1;
        if (y < 0 || y >= H_) continue;
        #pragma unroll
        for (int kj = 0; kj < 3; kj++) {
            const int xx = w + kj - 1;
            if (xx < 0 || xx >= W_) continue;
            const int xi = y * W_ + xx;
            #pragma unroll
            for (int c = 0; c < CG; c++)
                acc = fmaf(sw[c * K_ + ki * 3 + kj], xb[c * HW + xi], acc);
        }
    }
    g_off[(n * OFFC + oc) * HW + p] = acc;
}

// Deformable sampling + grouped einsum + per-channel sum/sumsq stats
__global__ void deform_kernel(const float* __restrict__ x,
                              const float* __restrict__ w_dc) {
    __shared__ float swg[CG * K_ * OG];   // layout [(c*9+k)*16 + o]
    __shared__ float s_sum[OG], s_sq[OG];
    const int g = blockIdx.y;
    const int n = blockIdx.z;
    const int tid = threadIdx.x;

    for (int i = tid; i < CG * K_ * OG; i += blockDim.x) {
        const int r = i >> 4, o = i & 15;
        swg[i] = w_dc[(g * OG + o) * (CG * K_) + r];
    }
    if (tid < OG) { s_sum[tid] = 0.f; s_sq[tid] = 0.f; }
    __syncthreads();

    const int p = blockIdx.x * blockDim.x + tid;
    const int h = p >> 6, w = p & 63;
    const float* xb   = x + (n * C_ + g * CG) * HW;
    const float* offp = g_off + (n * OFFC + g * 18) * HW + p;

    float acc[OG];
    #pragma unroll
    for (int o = 0; o < OG; o++) acc[o] = 0.f;

    for (int k = 0; k < K_; k++) {
        const int ki = k / 3, kj = k % 3;
        const float dy = offp[(2 * k)     * HW];
        const float dx = offp[(2 * k + 1) * HW];
        const float py = (float)(h - 1 + ki) + dy;
        const float px = (float)(w - 1 + kj) + dx;
        const float y0f = floorf(py), x0f = floorf(px);
        const float ly = py - y0f, lx = px - x0f;
        const int y0 = (int)y0f, x0 = (int)x0f;

        const bool vy0 = (y0 >= 0)  && (y0 < H_);
        const bool vy1 = (y0 >= -1) && (y0 < H_ - 1);
        const bool vx0 = (x0 >= 0)  && (x0 < W_);
        const bool vx1 = (x0 >= -1) && (x0 < W_ - 1);

        const float w00 = (1.f - ly) * (1.f - lx) * ((vy0 && vx0) ? 1.f : 0.f);
        const float w01 = (1.f - ly) * lx         * ((vy0 && vx1) ? 1.f : 0.f);
        const float w10 = ly * (1.f - lx)         * ((vy1 && vx0) ? 1.f : 0.f);
        const float w11 = ly * lx                 * ((vy1 && vx1) ? 1.f : 0.f);

        const int yc0 = min(max(y0, 0), H_ - 1);
        const int yc1 = min(max(y0 + 1, 0), H_ - 1);
        const int xc0 = min(max(x0, 0), W_ - 1);
        const int xc1 = min(max(x0 + 1, 0), W_ - 1);
        const int i00 = yc0 * W_ + xc0, i01 = yc0 * W_ + xc1;
        const int i10 = yc1 * W_ + xc0, i11 = yc1 * W_ + xc1;

        #pragma unroll
        for (int c = 0; c < CG; c++) {
            const float* xc = xb + c * HW;
            const float v = w00 * xc[i00] + w01 * xc[i01]
                          + w10 * xc[i10] + w11 * xc[i11];
            const float* wrow = &swg[(c * K_ + k) * OG];
            #pragma unroll
            for (int o = 0; o < OG; o++) acc[o] = fmaf(wrow[o], v, acc[o]);
        }
    }

    // write pre-normalization output
    float* pre = g_pre + (n * C_ + g * OG) * HW + p;
    #pragma unroll
    for (int o = 0; o < OG; o++) pre[o * HW] = acc[o];

    // per-channel stats: warp shuffle reduce -> shared -> global atomics
    const int lane = tid & 31;
    #pragma unroll
    for (int o = 0; o < OG; o++) {
        float s = acc[o];
        float q = acc[o] * acc[o];
        #pragma unroll
        for (int d = 16; d; d >>= 1) {
            s += __shfl_xor_sync(0xffffffffu, s, d);
            q += __shfl_xor_sync(0xffffffffu, q, d);
        }
        if (lane == 0) { atomicAdd(&s_sum[o], s); atomicAdd(&s_sq[o], q); }
    }
    __syncthreads();
    if (tid < OG) {
        atomicAdd(&g_sum[n * C_ + g * OG + tid], s_sum[tid]);
        atomicAdd(&g_sq [n * C_ + g * OG + tid], s_sq[tid]);
    }
}

// Normalize + exact GELU + transposed store
__global__ void norm_gelu_kernel(float* __restrict__ out) {
    const int oc = blockIdx.y;
    const int n  = blockIdx.z;
    const int p  = blockIdx.x * blockDim.x + threadIdx.x;

    const float s = g_sum[n * C_ + oc];
    const float q = g_sq [n * C_ + oc];
    const float mean = s * (1.f / HW);
    const float var  = q * (1.f / HW) - mean * mean;
    const float inv  = rsqrtf(var + 1e-5f);

    const float v = (g_pre[(n * C_ + oc) * HW + p] - mean) * inv;
    const float gel = 0.5f * v * (1.f + erff(v * 0.7071067811865475f));

    const int b = n >> 3, d = n & 7;   // n = b*8 + d
    out[((b * COUT + oc) * 8 + d) * HW + p] = gel;
}

extern "C" void kernel_launch(void* const* d_in, const int* in_sizes, int n_in,
                              void* d_out, int out_size) {
    const float* x     = (const float*)d_in[0];
    const float* w_off = (const float*)d_in[1];
    const float* b_off = (const float*)d_in[2];
    const float* w_dc  = (const float*)d_in[3];
    // d_in[4] = b_dc: a per-channel constant cancels exactly under the
    // per-(n,channel) mean subtraction and leaves variance unchanged -> unused.
    float* out = (float*)d_out;

    zero_stats_kernel<<<(N_ * COUT + 255) / 256, 256>>>();
    offset_conv_kernel<<<dim3(HW / 256, OFFC, N_), 256>>>(x, w_off, b_off);
    deform_kernel<<<dim3(HW / 128, G_, N_), 128>>>(x, w_dc);
    norm_gelu_kernel<<<dim3(HW / 256, COUT, N_), 256>>>(out);
}

// round 2
// speedup vs baseline: 1.2616x; 1.2616x over previous
#include <cuda_runtime.h>
#include <math.h>

#define G_   4
#define CG   16
#define H_   64
#define W_   64
#define HW   4096
#define COUT 64
#define N_   32

typedef unsigned long long u64;

// Scratch (static device globals; no runtime allocation)
__device__ float g_xt [N_ * G_ * HW * CG];   // x transposed: [n][g][p][c] (c contiguous)
__device__ float g_pre[N_ * COUT * HW];      // pre-norm conv output (b_dc cancels)
__device__ float g_sum[N_ * COUT];
__device__ float g_sq [N_ * COUT];

// ---- packed f32x2 helpers (Blackwell) ----
__device__ __forceinline__ u64 pack2(float lo, float hi) {
    u64 r; asm("mov.b64 %0,{%1,%2};" : "=l"(r) : "f"(lo), "f"(hi)); return r;
}
__device__ __forceinline__ float2 unpack2(u64 v) {
    float2 r; asm("mov.b64 {%0,%1},%2;" : "=f"(r.x), "=f"(r.y) : "l"(v)); return r;
}
__device__ __forceinline__ void ffma2(u64 &d, u64 a, u64 b) {
    asm("fma.rn.f32x2 %0,%1,%2,%0;" : "+l"(d) : "l"(a), "l"(b));
}
__device__ __forceinline__ u64 dup2(float v) { return pack2(v, v); }

__global__ void zero_stats_kernel() {
    int i = blockIdx.x * blockDim.x + threadIdx.x;
    if (i < N_ * COUT) { g_sum[i] = 0.f; g_sq[i] = 0.f; }
}

// x[n][c][p] -> x_t[n][g][p][cg]
__global__ void transpose_kernel(const float* __restrict__ x) {
    const int p = blockIdx.x * 256 + threadIdx.x;
    const int g = blockIdx.y, n = blockIdx.z;
    const float* xs = x + ((size_t)(n * 64 + g * 16)) * HW + p;
    float v[16];
    #pragma unroll
    for (int c = 0; c < 16; c++) v[c] = __ldg(xs + (size_t)c * HW);
    float4* dst = reinterpret_cast<float4*>(g_xt + (((size_t)(n * 4 + g)) * HW + p) * 16);
    dst[0] = make_float4(v[0],  v[1],  v[2],  v[3]);
    dst[1] = make_float4(v[4],  v[5],  v[6],  v[7]);
    dst[2] = make_float4(v[8],  v[9],  v[10], v[11]);
    dst[3] = make_float4(v[12], v[13], v[14], v[15]);
}

// Fused: offset conv (in-register) + deformable bilinear sampling + grouped
// einsum + per-(n,channel) sum/sumsq stats. One pixel per thread.
__global__ __launch_bounds__(128) void fused_kernel(const float* __restrict__ w_off,
                                                    const float* __restrict__ b_off,
                                                    const float* __restrict__ w_dc) {
    // conv weights packed over (dy,dx) pairs: swc[(c*9+pos)*9 + k]
    __shared__ u64 swc[16 * 9 * 9];
    // einsum weights packed over output pairs: swe[(c*9+k)*8 + op]
    __shared__ u64 swe[16 * 9 * 8];
    __shared__ u64 sb[9];
    __shared__ float s_dy[9 * 128], s_dx[9 * 128];
    __shared__ float s_sum[16], s_sq[16];

    const int tid = threadIdx.x;
    const int g = blockIdx.y, n = blockIdx.z;

    for (int i = tid; i < 16 * 9 * 9; i += 128) {
        const int c = i / 81, pos = (i / 9) % 9, k = i % 9;
        const float lo = w_off[((g * 18 + 2 * k)     * 16 + c) * 9 + pos];
        const float hi = w_off[((g * 18 + 2 * k + 1) * 16 + c) * 9 + pos];
        swc[i] = pack2(lo, hi);
    }
    for (int i = tid; i < 16 * 9 * 8; i += 128) {
        const int c = i / 72, k = (i / 8) % 9, op = i % 8;
        const float lo = w_dc[((g * 16 + 2 * op)     * 16 + c) * 9 + k];
        const float hi = w_dc[((g * 16 + 2 * op + 1) * 16 + c) * 9 + k];
        swe[i] = pack2(lo, hi);
    }
    if (tid < 9)  sb[tid] = pack2(b_off[g * 18 + 2 * tid], b_off[g * 18 + 2 * tid + 1]);
    if (tid < 16) { s_sum[tid] = 0.f; s_sq[tid] = 0.f; }
    __syncthreads();

    const int p = blockIdx.x * 128 + tid;
    const int h = p >> 6, w = p & 63;
    const float* xtg = g_xt + ((size_t)(n * 4 + g)) * HW * 16;

    // ---- Phase A: 18 offsets (9 packed (dy,dx) pairs) via grouped 3x3 conv ----
    u64 accoff[9];
    #pragma unroll
    for (int k = 0; k < 9; k++) accoff[k] = sb[k];

    #pragma unroll 1
    for (int pos = 0; pos < 9; pos++) {
        const int y  = h + pos / 3 - 1;
        const int xx = w + pos % 3 - 1;
        if (y < 0 || y >= H_ || xx < 0 || xx >= W_) continue;
        const float4* xp = reinterpret_cast<const float4*>(xtg + (y * 64 + xx) * 16);
        const float4 A = xp[0], B = xp[1], C = xp[2], D = xp[3];
        const float xv[16] = {A.x,A.y,A.z,A.w, B.x,B.y,B.z,B.w,
                              C.x,C.y,C.z,C.w, D.x,D.y,D.z,D.w};
        const u64* wr = &swc[pos * 9];
        #pragma unroll
        for (int c = 0; c < 16; c++) {
            const u64 xd = dup2(xv[c]);
            #pragma unroll
            for (int k = 0; k < 9; k++) ffma2(accoff[k], wr[c * 81 + k], xd);
        }
    }
    #pragma unroll
    for (int k = 0; k < 9; k++) {
        const float2 o = unpack2(accoff[k]);
        s_dy[k * 128 + tid] = o.x;
        s_dx[k * 128 + tid] = o.y;
    }

    // ---- Phase B: bilinear sampling + 16x16x9 einsum (packed over o-pairs) ----
    u64 acc[8];
    #pragma unroll
    for (int op = 0; op < 8; op++) acc[op] = 0ULL;

    #pragma unroll 1
    for (int k = 0; k < 9; k++) {
        const float dy = s_dy[k * 128 + tid];
        const float dx = s_dx[k * 128 + tid];
        const float py = (float)(h - 1 + k / 3) + dy;
        const float px = (float)(w - 1 + k % 3) + dx;
        const float y0f = floorf(py), x0f = floorf(px);
        const float ly = py - y0f, lx = px - x0f;
        const int y0 = (int)y0f, x0 = (int)x0f;

        const bool vy0 = (y0 >= 0)  && (y0 < H_);
        const bool vy1 = (y0 >= -1) && (y0 < H_ - 1);
        const bool vx0 = (x0 >= 0)  && (x0 < W_);
        const bool vx1 = (x0 >= -1) && (x0 < W_ - 1);

        const float w00 = (1.f - ly) * (1.f - lx) * ((vy0 && vx0) ? 1.f : 0.f);
        const float w01 = (1.f - ly) * lx         * ((vy0 && vx1) ? 1.f : 0.f);
        const float w10 = ly * (1.f - lx)         * ((vy1 && vx0) ? 1.f : 0.f);
        const float w11 = ly * lx                 * ((vy1 && vx1) ? 1.f : 0.f);

        const int yc0 = min(max(y0, 0), H_ - 1);
        const int yc1 = min(max(y0 + 1, 0), H_ - 1);
        const int xc0 = min(max(x0, 0), W_ - 1);
        const int xc1 = min(max(x0 + 1, 0), W_ - 1);

        const float4* q00 = reinterpret_cast<const float4*>(xtg + (yc0 * 64 + xc0) * 16);
        const float4* q01 = reinterpret_cast<const float4*>(xtg + (yc0 * 64 + xc1) * 16);
        const float4* q10 = reinterpret_cast<const float4*>(xtg + (yc1 * 64 + xc0) * 16);
        const float4* q11 = reinterpret_cast<const float4*>(xtg + (yc1 * 64 + xc1) * 16);

        float4 A[4], B4[4], C4[4], D4[4];
        #pragma unroll
        for (int j = 0; j < 4; j++) { A[j] = q00[j]; B4[j] = q01[j]; C4[j] = q10[j]; D4[j] = q11[j]; }

        const u64* we = &swe[k * 8];
        #pragma unroll
        for (int j = 0; j < 4; j++) {
            const float v0 = fmaf(w11, D4[j].x, fmaf(w10, C4[j].x, fmaf(w01, B4[j].x, w00 * A[j].x)));
            const float v1 = fmaf(w11, D4[j].y, fmaf(w10, C4[j].y, fmaf(w01, B4[j].y, w00 * A[j].y)));
            const float v2 = fmaf(w11, D4[j].z, fmaf(w10, C4[j].z, fmaf(w01, B4[j].z, w00 * A[j].z)));
            const float v3 = fmaf(w11, D4[j].w, fmaf(w10, C4[j].w, fmaf(w01, B4[j].w, w00 * A[j].w)));
            const u64 d0 = dup2(v0), d1 = dup2(v1), d2 = dup2(v2), d3 = dup2(v3);
            #pragma unroll
            for (int op = 0; op < 8; op++) ffma2(acc[op], we[(4 * j + 0) * 72 + op], d0);
            #pragma unroll
            for (int op = 0; op < 8; op++) ffma2(acc[op], we[(4 * j + 1) * 72 + op], d1);
            #pragma unroll
            for (int op = 0; op < 8; op++) ffma2(acc[op], we[(4 * j + 2) * 72 + op], d2);
            #pragma unroll
            for (int op = 0; op < 8; op++) ffma2(acc[op], we[(4 * j + 3) * 72 + op], d3);
        }
    }

    // ---- write pre-norm output + stats ----
    float ov[16];
    #pragma unroll
    for (int op = 0; op < 8; op++) {
        const float2 t = unpack2(acc[op]);
        ov[2 * op] = t.x; ov[2 * op + 1] = t.y;
    }
    float* pre = g_pre + ((size_t)(n * 64 + g * 16)) * HW + p;
    #pragma unroll
    for (int o = 0; o < 16; o++) pre[(size_t)o * HW] = ov[o];

    const int lane = tid & 31;
    #pragma unroll
    for (int o = 0; o < 16; o++) {
        float s = ov[o];
        float q = ov[o] * ov[o];
        #pragma unroll
        for (int d = 16; d; d >>= 1) {
            s += __shfl_xor_sync(0xffffffffu, s, d);
            q += __shfl_xor_sync(0xffffffffu, q, d);
        }
        if (lane == 0) { atomicAdd(&s_sum[o], s); atomicAdd(&s_sq[o], q); }
    }
    __syncthreads();
    if (tid < 16) {
        atomicAdd(&g_sum[n * 64 + g * 16 + tid], s_sum[tid]);
        atomicAdd(&g_sq [n * 64 + g * 16 + tid], s_sq[tid]);
    }
}

// Normalize + exact GELU + transposed store (vectorized float4)
__global__ void norm_gelu_kernel(float* __restrict__ out) {
    const int oc = blockIdx.y;
    const int n  = blockIdx.z;
    const int p4 = blockIdx.x * blockDim.x + threadIdx.x;   // 0..1023

    const float s = g_sum[n * 64 + oc];
    const float q = g_sq [n * 64 + oc];
    const float mean = s * (1.f / HW);
    const float var  = q * (1.f / HW) - mean * mean;
    const float inv  = rsqrtf(var + 1e-5f);

    const float4 v = reinterpret_cast<const float4*>(g_pre + ((size_t)(n * 64 + oc)) * HW)[p4];
    float4 r;
    {
        const float a = (v.x - mean) * inv; r.x = 0.5f * a * (1.f + erff(a * 0.7071067811865475f));
    }
    {
        const float a = (v.y - mean) * inv; r.y = 0.5f * a * (1.f + erff(a * 0.7071067811865475f));
    }
    {
        const float a = (v.z - mean) * inv; r.z = 0.5f * a * (1.f + erff(a * 0.7071067811865475f));
    }
    {
        const float a = (v.w - mean) * inv; r.w = 0.5f * a * (1.f + erff(a * 0.7071067811865475f));
    }

    const int b = n >> 3, d = n & 7;
    reinterpret_cast<float4*>(out + ((size_t)((b * 64 + oc) * 8 + d)) * HW)[p4] = r;
}

extern "C" void kernel_launch(void* const* d_in, const int* in_sizes, int n_in,
                              void* d_out, int out_size) {
    const float* x     = (const float*)d_in[0];
    const float* w_off = (const float*)d_in[1];
    const float* b_off = (const float*)d_in[2];
    const float* w_dc  = (const float*)d_in[3];
    // d_in[4] = b_dc: per-channel constant cancels under per-channel mean
    // subtraction; variance unchanged -> unused.
    float* out = (float*)d_out;

    zero_stats_kernel<<<(N_ * COUT + 255) / 256, 256>>>();
    transpose_kernel<<<dim3(HW / 256, G_, N_), 256>>>(x);
    fused_kernel<<<dim3(HW / 128, G_, N_), 128>>>(w_off, b_off, w_dc);
    norm_gelu_kernel<<<dim3(HW / (256 * 4), COUT, N_), 256>>>(out);
}